// round 1
// baseline (speedup 1.0000x reference)
#include <cuda_runtime.h>
#include <cuda_bf16.h>
#include <cstdint>

#define B_   64
#define T_   512
#define IN_  256
#define OUT_ 256
#define H_   512
#define MROWS (B_*T_)          // 32768
#define OUT_OFF (B_*T_*OUT_)   // 8388608 : offset of "hidden" in d_out

// ---------------- device scratch (no cudaMalloc allowed) ----------------
__device__ float2 g_u[B_*T_*H_];            // u = xp[:,:, :H] + i*xp[:,:,H:]   (128 MB)
__device__ float  g_outs[B_*T_*2*H_];       // concat(re,im) per (b,t)          (128 MB)

// ---------------- helpers ----------------
__device__ __forceinline__ float2 cmul(float2 a, float2 b) {
    return make_float2(a.x*b.x - a.y*b.y, a.x*b.y + a.y*b.x);
}

// =========================================================================
// Scan kernel: one block per batch row, 128 threads, 4 complex elems/thread
// =========================================================================

// Stockham radix-2 FFT-512 over shared ping-pong buffers.
// Caller must __syncthreads() after writing src. Returns buffer with result.
__device__ __forceinline__ float2* fft512(float2* src, float2* dst,
                                          const float2* TW, int tid, bool inverse)
{
    #pragma unroll
    for (int s = 0; s < 9; s++) {
        const int m = 1 << s;
        #pragma unroll
        for (int r = 0; r < 2; r++) {
            int idx = tid + 128*r;
            int k   = idx & (m - 1);
            float2 c0 = src[idx];
            float2 c1 = src[idx + 256];
            float2 w  = TW[idx - k];
            float  wy = inverse ? -w.y : w.y;
            float2 sum = make_float2(c0.x + c1.x, c0.y + c1.y);
            float2 dif = make_float2(c0.x - c1.x, c0.y - c1.y);
            float2 tw  = make_float2(w.x*dif.x - wy*dif.y, w.x*dif.y + wy*dif.x);
            dst[2*idx - k]     = sum;
            dst[2*idx - k + m] = tw;
        }
        float2* tmp = src; src = dst; dst = tmp;
        __syncthreads();
    }
    return src;   // after 9 swaps, result buffer
}

__global__ __launch_bounds__(128)
void scan_kernel(const float* __restrict__ h0,
                 const float* __restrict__ b_h,
                 const float* __restrict__ d1,
                 const float* __restrict__ d2,
                 const float* __restrict__ d3,
                 const float* __restrict__ r1re, const float* __restrict__ r1im,
                 const float* __restrict__ r2re, const float* __restrict__ r2im,
                 const int*   __restrict__ perm,
                 float* __restrict__ dout)
{
    __shared__ float2 SH[512];      // persistent hidden state
    __shared__ float2 SA[512], SB[512];
    __shared__ float2 TW[256];
    __shared__ float2 E1[512], E2[512], E3[512];
    __shared__ float2 V1[512], V2[512];
    __shared__ float  BH[512];
    __shared__ int    PERM[512];
    __shared__ float2 RED[4];
    __shared__ float  FAC[2];

    const int b    = blockIdx.x;
    const int tid  = threadIdx.x;
    const int lane = tid & 31;
    const int wid  = tid >> 5;

    // ---- init constants ----
    for (int i = tid; i < 512; i += 128) {
        float sn, cs;
        sincosf(d1[i], &sn, &cs); E1[i] = make_float2(cs, sn);
        sincosf(d2[i], &sn, &cs); E2[i] = make_float2(cs, sn);
        sincosf(d3[i], &sn, &cs); E3[i] = make_float2(cs, sn);
        V1[i] = make_float2(r1re[i], r1im[i]);
        V2[i] = make_float2(r2re[i], r2im[i]);
        BH[i] = b_h[i];
        PERM[i] = perm[i];
        SH[i] = make_float2(h0[b*1024 + i], h0[b*1024 + 512 + i]);
    }
    for (int i = tid; i < 256; i += 128) {
        float ang = -6.283185307179586f * (float)i / 512.0f;
        float sn, cs; sincosf(ang, &sn, &cs);
        TW[i] = make_float2(cs, sn);
    }
    __syncthreads();

    // ---- fac1/fac2 = 2 / ||v||^2 ----
    {
        float n1 = 0.f, n2 = 0.f;
        #pragma unroll
        for (int r = 0; r < 4; r++) {
            int idx = tid + 128*r;
            n1 += V1[idx].x*V1[idx].x + V1[idx].y*V1[idx].y;
            n2 += V2[idx].x*V2[idx].x + V2[idx].y*V2[idx].y;
        }
        #pragma unroll
        for (int off = 16; off; off >>= 1) {
            n1 += __shfl_xor_sync(0xffffffffu, n1, off);
            n2 += __shfl_xor_sync(0xffffffffu, n2, off);
        }
        if (lane == 0) RED[wid] = make_float2(n1, n2);
        __syncthreads();
        if (tid == 0) {
            float a  = ((RED[0].x + RED[1].x) + (RED[2].x + RED[3].x));
            float bb = ((RED[0].y + RED[1].y) + (RED[2].y + RED[3].y));
            FAC[0] = 2.f / a;
            FAC[1] = 2.f / bb;
        }
        __syncthreads();
    }
    const float fac1 = FAC[0];
    const float fac2 = FAC[1];
    const int   brow = b * T_;

    // ---- sequential scan over t ----
    for (int t = 0; t < T_; t++) {
        // prefetch u_t (long latency hidden behind FFTs)
        float2 u0[4];
        {
            int ubase = (brow + t) * H_;
            #pragma unroll
            for (int r = 0; r < 4; r++) u0[r] = g_u[ubase + tid + 128*r];
        }

        // s = h * e1  -> SA
        #pragma unroll
        for (int r = 0; r < 4; r++) {
            int idx = tid + 128*r;
            SA[idx] = cmul(SH[idx], E1[idx]);
        }
        __syncthreads();

        // forward FFT
        float2* cur = fft512(SA, SB, TW, tid, false);

        // reflect with v1:  z -= fac1 * (z . conj(v1)) * v1
        {
            float2 dacc = make_float2(0.f, 0.f);
            #pragma unroll
            for (int r = 0; r < 4; r++) {
                int idx = tid + 128*r;
                float2 z = cur[idx], v = V1[idx];
                dacc.x += z.x*v.x + z.y*v.y;
                dacc.y += z.y*v.x - z.x*v.y;
            }
            #pragma unroll
            for (int off = 16; off; off >>= 1) {
                dacc.x += __shfl_xor_sync(0xffffffffu, dacc.x, off);
                dacc.y += __shfl_xor_sync(0xffffffffu, dacc.y, off);
            }
            if (lane == 0) RED[wid] = dacc;
            __syncthreads();
            float2 dot = make_float2((RED[0].x + RED[1].x) + (RED[2].x + RED[3].x),
                                     (RED[0].y + RED[1].y) + (RED[2].y + RED[3].y));
            dot.x *= fac1; dot.y *= fac1;
            #pragma unroll
            for (int r = 0; r < 4; r++) {
                int idx = tid + 128*r;
                float2 v = V1[idx];
                float2 z = cur[idx];
                z.x -= dot.x*v.x - dot.y*v.y;
                z.y -= dot.x*v.y + dot.y*v.x;
                cur[idx] = z;
            }
            __syncthreads();
        }

        // permute + *e2  (cur==SB here, write into SA)
        {
            float2* oth = (cur == SA) ? SB : SA;
            #pragma unroll
            for (int r = 0; r < 4; r++) {
                int idx = tid + 128*r;
                float2 z = cur[PERM[idx]];
                oth[idx] = cmul(z, E2[idx]);
            }
            __syncthreads();
            cur = oth;
        }

        // inverse FFT (1/512 folded into epilogue; reflection is linear)
        cur = fft512(cur, (cur == SA) ? SB : SA, TW, tid, true);

        // reflect with v2, then *e3, *(1/512), add u, modReLU, write outs
        {
            float2 dacc = make_float2(0.f, 0.f);
            #pragma unroll
            for (int r = 0; r < 4; r++) {
                int idx = tid + 128*r;
                float2 z = cur[idx], v = V2[idx];
                dacc.x += z.x*v.x + z.y*v.y;
                dacc.y += z.y*v.x - z.x*v.y;
            }
            #pragma unroll
            for (int off = 16; off; off >>= 1) {
                dacc.x += __shfl_xor_sync(0xffffffffu, dacc.x, off);
                dacc.y += __shfl_xor_sync(0xffffffffu, dacc.y, off);
            }
            if (lane == 0) RED[wid] = dacc;
            __syncthreads();
            float2 dot = make_float2((RED[0].x + RED[1].x) + (RED[2].x + RED[3].x),
                                     (RED[0].y + RED[1].y) + (RED[2].y + RED[3].y));
            dot.x *= fac2; dot.y *= fac2;

            const int orow = (brow + t) * (2*H_);
            const float inv512 = 1.0f / 512.0f;
            #pragma unroll
            for (int r = 0; r < 4; r++) {
                int idx = tid + 128*r;
                float2 z = cur[idx], v = V2[idx];
                z.x -= dot.x*v.x - dot.y*v.y;
                z.y -= dot.x*v.y + dot.y*v.x;
                float2 e = E3[idx];
                float2 s = make_float2((z.x*e.x - z.y*e.y) * inv512,
                                       (z.x*e.y + z.y*e.x) * inv512);
                float2 pre = make_float2(u0[r].x + s.x, u0[r].y + s.y);
                float norm = sqrtf(pre.x*pre.x + pre.y*pre.y);
                float sc = fmaxf(norm + BH[idx], 0.f) / (norm + 1e-6f);
                float2 nw = make_float2(pre.x*sc, pre.y*sc);
                SH[idx] = nw;                          // owner-only: no race
                g_outs[orow + idx]        = nw.x;
                g_outs[orow + 512 + idx]  = nw.y;
            }
            // no barrier needed: next iteration only touches owner slots of
            // SH/SA, and cur (SB) is never written before the next barrier.
        }
    }

    // final hidden state
    #pragma unroll
    for (int r = 0; r < 4; r++) {
        int idx = tid + 128*r;
        dout[OUT_OFF + b*1024 + idx]       = SH[idx].x;
        dout[OUT_OFF + b*1024 + 512 + idx] = SH[idx].y;
    }
}

// =========================================================================
// bf16x3 split-precision GEMM:  C[M,N] = A[M,K] * W[N,K]^T (+bias)
// MODE 0: A = x param,      epilogue -> g_u split (re/im)
// MODE 1: A = g_outs,       epilogue -> C param + bias
// BM=128 BN=64 BK=32, 256 threads, warp tile 32x32, mma.m16n8k16
// =========================================================================
#define MMA16816(d, a, b)                                                     \
    asm volatile("mma.sync.aligned.m16n8k16.row.col.f32.bf16.bf16.f32 "       \
                 "{%0,%1,%2,%3}, {%4,%5,%6,%7}, {%8,%9}, {%0,%1,%2,%3};\n"    \
                 : "+f"(d[0]), "+f"(d[1]), "+f"(d[2]), "+f"(d[3])             \
                 : "r"(a[0]), "r"(a[1]), "r"(a[2]), "r"(a[3]),                \
                   "r"(b[0]), "r"(b[1]))

template<int MODE>
__global__ __launch_bounds__(256)
void gemm_bf16x3(const float* __restrict__ Ap,
                 const float* __restrict__ W,
                 const float* __restrict__ bias,
                 float* __restrict__ C,
                 int M, int N, int K)
{
    const int BK = 32;
    __shared__ __nv_bfloat16 As[2][128][40];   // [hi/lo][m][k] (pad->40 to kill conflicts)
    __shared__ __nv_bfloat16 Bs[2][64][40];    // [hi/lo][n][k]

    const float* A = (MODE == 1) ? (const float*)g_outs : Ap;

    const int tid = threadIdx.x;
    const int wid = tid >> 5, lane = tid & 31;
    const int wm = wid >> 1, wn = wid & 1;       // 4x2 warps
    const int groupID = lane >> 2, tig = lane & 3;

    const int bm0 = blockIdx.y * 128;
    const int bn0 = blockIdx.x * 64;

    float acc[2][4][4];
    #pragma unroll
    for (int mi = 0; mi < 2; mi++)
        #pragma unroll
        for (int ni = 0; ni < 4; ni++)
            #pragma unroll
            for (int j = 0; j < 4; j++) acc[mi][ni][j] = 0.f;

    for (int k0 = 0; k0 < K; k0 += BK) {
        // ---- load A tile 128x32 (4 float4 per thread) ----
        #pragma unroll
        for (int i = 0; i < 4; i++) {
            int f = tid + 256*i;
            int r = f >> 3, c = (f & 7) * 4;
            float4 v = *(const float4*)(A + (size_t)(bm0 + r)*K + k0 + c);
            const float* pv = (const float*)&v;
            #pragma unroll
            for (int j = 0; j < 4; j++) {
                __nv_bfloat16 hi = __float2bfloat16(pv[j]);
                __nv_bfloat16 lo = __float2bfloat16(pv[j] - __bfloat162float(hi));
                As[0][r][c + j] = hi;
                As[1][r][c + j] = lo;
            }
        }
        // ---- load B tile 64x32 (2 float4 per thread) ----
        #pragma unroll
        for (int i = 0; i < 2; i++) {
            int f = tid + 256*i;
            int r = f >> 3, c = (f & 7) * 4;
            float4 v = *(const float4*)(W + (size_t)(bn0 + r)*K + k0 + c);
            const float* pv = (const float*)&v;
            #pragma unroll
            for (int j = 0; j < 4; j++) {
                __nv_bfloat16 hi = __float2bfloat16(pv[j]);
                __nv_bfloat16 lo = __float2bfloat16(pv[j] - __bfloat162float(hi));
                Bs[0][r][c + j] = hi;
                Bs[1][r][c + j] = lo;
            }
        }
        __syncthreads();

        #pragma unroll
        for (int kk = 0; kk < 2; kk++) {
            const int kb = kk * 16;
            uint32_t aH[2][4], aL[2][4], bH[4][2], bL[4][2];
            #pragma unroll
            for (int mi = 0; mi < 2; mi++) {
                int r0 = wm*32 + mi*16 + groupID;
                int r1 = r0 + 8;
                aH[mi][0] = *(const uint32_t*)&As[0][r0][kb + 2*tig];
                aH[mi][1] = *(const uint32_t*)&As[0][r1][kb + 2*tig];
                aH[mi][2] = *(const uint32_t*)&As[0][r0][kb + 2*tig + 8];
                aH[mi][3] = *(const uint32_t*)&As[0][r1][kb + 2*tig + 8];
                aL[mi][0] = *(const uint32_t*)&As[1][r0][kb + 2*tig];
                aL[mi][1] = *(const uint32_t*)&As[1][r1][kb + 2*tig];
                aL[mi][2] = *(const uint32_t*)&As[1][r0][kb + 2*tig + 8];
                aL[mi][3] = *(const uint32_t*)&As[1][r1][kb + 2*tig + 8];
            }
            #pragma unroll
            for (int ni = 0; ni < 4; ni++) {
                int cc = wn*32 + ni*8 + groupID;
                bH[ni][0] = *(const uint32_t*)&Bs[0][cc][kb + 2*tig];
                bH[ni][1] = *(const uint32_t*)&Bs[0][cc][kb + 2*tig + 8];
                bL[ni][0] = *(const uint32_t*)&Bs[1][cc][kb + 2*tig];
                bL[ni][1] = *(const uint32_t*)&Bs[1][cc][kb + 2*tig + 8];
            }
            #pragma unroll
            for (int mi = 0; mi < 2; mi++)
                #pragma unroll
                for (int ni = 0; ni < 4; ni++) {
                    MMA16816(acc[mi][ni], aH[mi], bH[ni]);
                    MMA16816(acc[mi][ni], aH[mi], bL[ni]);
                    MMA16816(acc[mi][ni], aL[mi], bH[ni]);
                }
        }
        __syncthreads();
    }

    // ---- epilogue ----
    #pragma unroll
    for (int mi = 0; mi < 2; mi++) {
        #pragma unroll
        for (int ni = 0; ni < 4; ni++) {
            int r0 = bm0 + wm*32 + mi*16 + groupID;
            int c0 = bn0 + wn*32 + ni*8 + 2*tig;
            float v00 = acc[mi][ni][0], v01 = acc[mi][ni][1];
            float v10 = acc[mi][ni][2], v11 = acc[mi][ni][3];
            if (MODE == 0) {
                // write u split: col<512 -> real, else imag
                #pragma unroll
                for (int q = 0; q < 4; q++) {
                    int rr = (q < 2) ? r0 : (r0 + 8);
                    int cc = (q & 1) ? (c0 + 1) : c0;
                    float vv = (q==0)?v00:(q==1)?v01:(q==2)?v10:v11;
                    if (cc < 512) g_u[(size_t)rr*512 + cc].x = vv;
                    else          g_u[(size_t)rr*512 + cc - 512].y = vv;
                }
            } else {
                float b0 = bias[c0], b1 = bias[c0 + 1];
                C[(size_t)r0*N + c0]         = v00 + b0;
                C[(size_t)r0*N + c0 + 1]     = v01 + b1;
                C[(size_t)(r0+8)*N + c0]     = v10 + b0;
                C[(size_t)(r0+8)*N + c0 + 1] = v11 + b1;
            }
        }
    }
}

// =========================================================================
extern "C" void kernel_launch(void* const* d_in, const int* in_sizes, int n_in,
                              void* d_out, int out_size)
{
    const float* x    = (const float*)d_in[0];
    const float* h0   = (const float*)d_in[1];
    const float* itoh = (const float*)d_in[2];
    const float* fcw  = (const float*)d_in[3];
    const float* fcb  = (const float*)d_in[4];
    const float* bh   = (const float*)d_in[5];
    const float* d1   = (const float*)d_in[6];
    const float* d2   = (const float*)d_in[7];
    const float* d3   = (const float*)d_in[8];
    const float* r1re = (const float*)d_in[9];
    const float* r1im = (const float*)d_in[10];
    const float* r2re = (const float*)d_in[11];
    const float* r2im = (const float*)d_in[12];
    const int*   perm = (const int*)d_in[13];
    float* out = (float*)d_out;

    // GEMM1: u = x @ itoh_w^T  (M=32768, N=1024, K=256) -> g_u
    gemm_bf16x3<0><<<dim3(1024/64, MROWS/128), 256>>>(x, itoh, nullptr, nullptr,
                                                      MROWS, 1024, 256);
    // sequential scan, one block per batch row
    scan_kernel<<<B_, 128>>>(h0, bh, d1, d2, d3, r1re, r1im, r2re, r2im, perm, out);
    // GEMM2: outputs = outs @ fc_w^T + fc_b  (M=32768, N=256, K=1024) -> d_out
    gemm_bf16x3<1><<<dim3(256/64, MROWS/128), 256>>>(nullptr, fcw, fcb, out,
                                                     MROWS, 256, 1024);
}

// round 2
// speedup vs baseline: 1.5948x; 1.5948x over previous
#include <cuda_runtime.h>
#include <cuda_bf16.h>
#include <cstdint>

#define B_   64
#define T_   512
#define IN_  256
#define OUT_ 256
#define H_   512
#define MROWS (B_*T_)          // 32768
#define OUT_OFF (B_*T_*OUT_)   // 8388608 : offset of "hidden" in d_out

// ---------------- device scratch (no cudaMalloc allowed) ----------------
__device__ __align__(16) float2 g_u[MROWS*H_];                 // 128 MB
__device__ __align__(16) __nv_bfloat16 g_outsH[MROWS*2*H_];    // 64 MB
__device__ __align__(16) __nv_bfloat16 g_outsL[MROWS*2*H_];    // 64 MB
__device__ __align__(16) __nv_bfloat16 g_xH[MROWS*IN_];
__device__ __align__(16) __nv_bfloat16 g_xL[MROWS*IN_];
__device__ __align__(16) __nv_bfloat16 g_w1H[2*H_*IN_];
__device__ __align__(16) __nv_bfloat16 g_w1L[2*H_*IN_];
__device__ __align__(16) __nv_bfloat16 g_w2H[OUT_*2*H_];
__device__ __align__(16) __nv_bfloat16 g_w2L[OUT_*2*H_];

__device__ __forceinline__ float2 cmul(float2 a, float2 b) {
    return make_float2(a.x*b.x - a.y*b.y, a.x*b.y + a.y*b.x);
}

// =========================================================================
// split kernels: fp32 -> (hi, lo) bf16.  WHICH selects destination globals.
// =========================================================================
template<int WHICH>
__global__ void split_kernel(const float* __restrict__ src, int n4)
{
    __nv_bfloat16 *hi, *lo;
    if (WHICH == 0) { hi = g_xH;  lo = g_xL;  }
    if (WHICH == 1) { hi = g_w1H; lo = g_w1L; }
    if (WHICH == 2) { hi = g_w2H; lo = g_w2L; }
    int i = blockIdx.x * blockDim.x + threadIdx.x;
    if (i >= n4) return;
    float4 v = ((const float4*)src)[i];
    const float* pv = (const float*)&v;
    #pragma unroll
    for (int j = 0; j < 4; j++) {
        __nv_bfloat16 h = __float2bfloat16(pv[j]);
        hi[4*i + j] = h;
        lo[4*i + j] = __float2bfloat16(pv[j] - __bfloat162float(h));
    }
}

// =========================================================================
// Scan kernel: radix-4 Stockham FFT-512, h register-resident, 10 syncs/step
// =========================================================================

// radix-4 Stockham stage, parameter M; 128 threads, one butterfly each.
// INV=0: forward (twiddles as given, quarter = -i). INV=1: conj twiddles, +i.
template<int M, int INV>
__device__ __forceinline__ void r4(const float2* __restrict__ src,
                                   float2* __restrict__ dst,
                                   float2 w1, float2 w2, int tid)
{
    const float w1y = INV ? -w1.y : w1.y;
    const float w2y = INV ? -w2.y : w2.y;
    int k = tid & (M - 1);
    float2 x0 = src[tid], x1 = src[tid+128], x2 = src[tid+256], x3 = src[tid+384];
    float2 a   = make_float2(x0.x + x2.x, x0.y + x2.y);
    float2 s02 = make_float2(x0.x - x2.x, x0.y - x2.y);
    float2 c   = make_float2(x1.x + x3.x, x1.y + x3.y);
    float2 s13 = make_float2(x1.x - x3.x, x1.y - x3.y);
    float2 b = make_float2(w1.x*s02.x - w1y*s02.y, w1.x*s02.y + w1y*s02.x);
    float2 q = INV ? make_float2(-s13.y, s13.x) : make_float2(s13.y, -s13.x);
    float2 d = make_float2(w1.x*q.x - w1y*q.y, w1.x*q.y + w1y*q.x);
    int o = 4*tid - 3*k;
    dst[o]     = make_float2(a.x + c.x, a.y + c.y);
    dst[o + M] = make_float2(b.x + d.x, b.y + d.y);
    float2 ac = make_float2(a.x - c.x, a.y - c.y);
    float2 bd = make_float2(b.x - d.x, b.y - d.y);
    dst[o + 2*M] = make_float2(w2.x*ac.x - w2y*ac.y, w2.x*ac.y + w2y*ac.x);
    dst[o + 3*M] = make_float2(w2.x*bd.x - w2y*bd.y, w2.x*bd.y + w2y*bd.x);
}

// same stage but inputs from registers (fused stage 1, M=1, k=0)
template<int INV>
__device__ __forceinline__ void r4_reg(float2 x0, float2 x1, float2 x2, float2 x3,
                                       float2* __restrict__ dst,
                                       float2 w1, float2 w2, int tid)
{
    const float w1y = INV ? -w1.y : w1.y;
    const float w2y = INV ? -w2.y : w2.y;
    float2 a   = make_float2(x0.x + x2.x, x0.y + x2.y);
    float2 s02 = make_float2(x0.x - x2.x, x0.y - x2.y);
    float2 c   = make_float2(x1.x + x3.x, x1.y + x3.y);
    float2 s13 = make_float2(x1.x - x3.x, x1.y - x3.y);
    float2 b = make_float2(w1.x*s02.x - w1y*s02.y, w1.x*s02.y + w1y*s02.x);
    float2 q = INV ? make_float2(-s13.y, s13.x) : make_float2(s13.y, -s13.x);
    float2 d = make_float2(w1.x*q.x - w1y*q.y, w1.x*q.y + w1y*q.x);
    int o = 4*tid;
    dst[o]   = make_float2(a.x + c.x, a.y + c.y);
    dst[o+1] = make_float2(b.x + d.x, b.y + d.y);
    float2 ac = make_float2(a.x - c.x, a.y - c.y);
    float2 bd = make_float2(b.x - d.x, b.y - d.y);
    dst[o+2] = make_float2(w2.x*ac.x - w2y*ac.y, w2.x*ac.y + w2y*ac.x);
    dst[o+3] = make_float2(w2.x*bd.x - w2y*bd.y, w2.x*bd.y + w2y*bd.x);
}

__global__ __launch_bounds__(128)
void scan_kernel(const float* __restrict__ h0,
                 const float* __restrict__ b_h,
                 const float* __restrict__ d1,
                 const float* __restrict__ d2,
                 const float* __restrict__ d3,
                 const float* __restrict__ r1re, const float* __restrict__ r1im,
                 const float* __restrict__ r2re, const float* __restrict__ r2im,
                 const int*   __restrict__ perm,
                 float* __restrict__ dout)
{
    __shared__ float2 SA[512], SB[512];
    __shared__ float2 V1s[512];
    __shared__ float2 RED[4];
    __shared__ float  FAC[2];

    const int b = blockIdx.x, tid = threadIdx.x;
    const int lane = tid & 31, wid = tid >> 5;

    // ---- per-thread constants at indices idx_r = tid + 128r ----
    float2 h[4], e1r[4], e2r[4], e3r[4], v1r[4], v2r[4];
    float bhr[4]; int pr[4];
    #pragma unroll
    for (int r = 0; r < 4; r++) {
        int idx = tid + 128*r;
        float sn, cs;
        sincosf(d1[idx], &sn, &cs); e1r[r] = make_float2(cs, sn);
        sincosf(d2[idx], &sn, &cs); e2r[r] = make_float2(cs, sn);
        sincosf(d3[idx], &sn, &cs); e3r[r] = make_float2(cs, sn);
        v1r[r] = make_float2(r1re[idx], r1im[idx]);
        v2r[r] = make_float2(r2re[idx], r2im[idx]);
        V1s[idx] = v1r[r];
        bhr[r] = b_h[idx];
        pr[r]  = perm[idx];
        h[r]   = make_float2(h0[b*1024 + idx], h0[b*1024 + 512 + idx]);
    }

    // ---- per-thread twiddles, stages m = 1,4,16,64 ----
    float2 W1[4], W2[4];
    #pragma unroll
    for (int s = 0; s < 4; s++) {
        int m = 1 << (2*s);
        int base = tid & ~(m - 1);
        float sn, cs;
        float a1 = -6.283185307179586f * (float)base / 512.0f;
        sincosf(a1, &sn, &cs); W1[s] = make_float2(cs, sn);
        float a2 = -6.283185307179586f * (float)(2*base) / 512.0f;
        sincosf(a2, &sn, &cs); W2[s] = make_float2(cs, sn);
    }

    // ---- fac1/fac2 = 2/||v||^2 ----
    {
        float n1 = 0.f, n2 = 0.f;
        #pragma unroll
        for (int r = 0; r < 4; r++) {
            n1 += v1r[r].x*v1r[r].x + v1r[r].y*v1r[r].y;
            n2 += v2r[r].x*v2r[r].x + v2r[r].y*v2r[r].y;
        }
        #pragma unroll
        for (int off = 16; off; off >>= 1) {
            n1 += __shfl_xor_sync(0xffffffffu, n1, off);
            n2 += __shfl_xor_sync(0xffffffffu, n2, off);
        }
        if (lane == 0) RED[wid] = make_float2(n1, n2);
        __syncthreads();
        if (tid == 0) {
            float a  = (RED[0].x + RED[1].x) + (RED[2].x + RED[3].x);
            float bb = (RED[0].y + RED[1].y) + (RED[2].y + RED[3].y);
            FAC[0] = 2.f / a; FAC[1] = 2.f / bb;
        }
        __syncthreads();
    }
    const float fac1 = FAC[0], fac2 = FAC[1];
    const int brow = b * T_;
    const float inv512 = 1.0f / 512.0f;

    for (int t = 0; t < T_; t++) {
        // prefetch u_t
        float2 u0[4];
        {
            const float2* up = g_u + (size_t)(brow + t) * H_;
            #pragma unroll
            for (int r = 0; r < 4; r++) u0[r] = up[tid + 128*r];
        }

        // FFT stage 1 (m=1), fused h*e1, regs -> SA
        r4_reg<0>(cmul(h[0], e1r[0]), cmul(h[1], e1r[1]),
                  cmul(h[2], e1r[2]), cmul(h[3], e1r[3]),
                  SA, W1[0], W2[0], tid);
        __syncthreads();                        // 1
        r4<4,  0>(SA, SB, W1[1], W2[1], tid);  __syncthreads();   // 2
        r4<16, 0>(SB, SA, W1[2], W2[2], tid);  __syncthreads();   // 3
        r4<64, 0>(SA, SB, W1[3], W2[3], tid);  __syncthreads();   // 4

        // stage 5: radix-2 m=256 (no twiddle), SB -> regs z; z -> SA; dot1
        float2 z[4];
        {
            float2 a0 = SB[tid], a1 = SB[tid+128], a2 = SB[tid+256], a3 = SB[tid+384];
            z[0] = make_float2(a0.x + a2.x, a0.y + a2.y);
            z[2] = make_float2(a0.x - a2.x, a0.y - a2.y);
            z[1] = make_float2(a1.x + a3.x, a1.y + a3.y);
            z[3] = make_float2(a1.x - a3.x, a1.y - a3.y);
        }
        SA[tid] = z[0]; SA[tid+128] = z[1]; SA[tid+256] = z[2]; SA[tid+384] = z[3];
        {
            float dx = 0.f, dy = 0.f;
            #pragma unroll
            for (int r = 0; r < 4; r++) {
                dx += z[r].x*v1r[r].x + z[r].y*v1r[r].y;
                dy += z[r].y*v1r[r].x - z[r].x*v1r[r].y;
            }
            #pragma unroll
            for (int off = 16; off; off >>= 1) {
                dx += __shfl_xor_sync(0xffffffffu, dx, off);
                dy += __shfl_xor_sync(0xffffffffu, dy, off);
            }
            if (lane == 0) RED[wid] = make_float2(dx, dy);
        }
        __syncthreads();                        // 5
        float2 dot1;
        dot1.x = ((RED[0].x + RED[1].x) + (RED[2].x + RED[3].x)) * fac1;
        dot1.y = ((RED[0].y + RED[1].y) + (RED[2].y + RED[3].y)) * fac1;

        // IFFT stage 1: fused reflect-subtract + permute + e2, SA -> SB
        {
            float2 x[4];
            #pragma unroll
            for (int i = 0; i < 4; i++) {
                int p = pr[i];
                float2 zz = SA[p], vv = V1s[p];
                zz.x -= dot1.x*vv.x - dot1.y*vv.y;
                zz.y -= dot1.x*vv.y + dot1.y*vv.x;
                x[i] = cmul(zz, e2r[i]);
            }
            r4_reg<1>(x[0], x[1], x[2], x[3], SB, W1[0], W2[0], tid);
        }
        __syncthreads();                        // 6
        r4<4,  1>(SB, SA, W1[1], W2[1], tid);  __syncthreads();   // 7
        r4<16, 1>(SA, SB, W1[2], W2[2], tid);  __syncthreads();   // 8
        r4<64, 1>(SB, SA, W1[3], W2[3], tid);  __syncthreads();   // 9

        // IFFT stage 5: SA -> regs z; dot2
        {
            float2 a0 = SA[tid], a1 = SA[tid+128], a2 = SA[tid+256], a3 = SA[tid+384];
            z[0] = make_float2(a0.x + a2.x, a0.y + a2.y);
            z[2] = make_float2(a0.x - a2.x, a0.y - a2.y);
            z[1] = make_float2(a1.x + a3.x, a1.y + a3.y);
            z[3] = make_float2(a1.x - a3.x, a1.y - a3.y);
        }
        {
            float dx = 0.f, dy = 0.f;
            #pragma unroll
            for (int r = 0; r < 4; r++) {
                dx += z[r].x*v2r[r].x + z[r].y*v2r[r].y;
                dy += z[r].y*v2r[r].x - z[r].x*v2r[r].y;
            }
            #pragma unroll
            for (int off = 16; off; off >>= 1) {
                dx += __shfl_xor_sync(0xffffffffu, dx, off);
                dy += __shfl_xor_sync(0xffffffffu, dy, off);
            }
            if (lane == 0) RED[wid] = make_float2(dx, dy);
        }
        __syncthreads();                        // 10
        float2 dot2;
        dot2.x = ((RED[0].x + RED[1].x) + (RED[2].x + RED[3].x)) * fac2;
        dot2.y = ((RED[0].y + RED[1].y) + (RED[2].y + RED[3].y)) * fac2;

        // epilogue: reflect2 + e3 + 1/512 + u + modReLU, all in registers
        const int orow = (brow + t) * (2*H_);
        #pragma unroll
        for (int r = 0; r < 4; r++) {
            float2 zz = z[r], vv = v2r[r];
            zz.x -= dot2.x*vv.x - dot2.y*vv.y;
            zz.y -= dot2.x*vv.y + dot2.y*vv.x;
            float2 e = e3r[r];
            float2 s = make_float2((zz.x*e.x - zz.y*e.y) * inv512,
                                   (zz.x*e.y + zz.y*e.x) * inv512);
            float2 pre = make_float2(u0[r].x + s.x, u0[r].y + s.y);
            float norm = sqrtf(pre.x*pre.x + pre.y*pre.y);
            float sc = fmaxf(norm + bhr[r], 0.f) / (norm + 1e-6f);
            float2 nw = make_float2(pre.x*sc, pre.y*sc);
            h[r] = nw;
            int idx = tid + 128*r;
            __nv_bfloat16 hx = __float2bfloat16(nw.x);
            __nv_bfloat16 hy = __float2bfloat16(nw.y);
            g_outsH[orow + idx]       = hx;
            g_outsL[orow + idx]       = __float2bfloat16(nw.x - __bfloat162float(hx));
            g_outsH[orow + 512 + idx] = hy;
            g_outsL[orow + 512 + idx] = __float2bfloat16(nw.y - __bfloat162float(hy));
        }
        // next iteration's first SA write is after sync 10 -> safe
    }

    #pragma unroll
    for (int r = 0; r < 4; r++) {
        int idx = tid + 128*r;
        dout[OUT_OFF + b*1024 + idx]       = h[r].x;
        dout[OUT_OFF + b*1024 + 512 + idx] = h[r].y;
    }
}

// =========================================================================
// bf16x3 GEMM with pre-split operands + cp.async double buffering
// C[M,N] = A[M,K] * W[N,K]^T (+bias).  BM=128 BN=64 BK=32, 256 thr.
// MODE 0: A=g_x*, W=g_w1*, epilogue -> g_u split re/im
// MODE 1: A=g_outs*, W=g_w2*, epilogue -> C + bias
// =========================================================================
#define MMA16816(d, a, b)                                                     \
    asm volatile("mma.sync.aligned.m16n8k16.row.col.f32.bf16.bf16.f32 "       \
                 "{%0,%1,%2,%3}, {%4,%5,%6,%7}, {%8,%9}, {%0,%1,%2,%3};\n"    \
                 : "+f"(d[0]), "+f"(d[1]), "+f"(d[2]), "+f"(d[3])             \
                 : "r"(a[0]), "r"(a[1]), "r"(a[2]), "r"(a[3]),                \
                   "r"(b[0]), "r"(b[1]))

__device__ __forceinline__ void cp16(void* dst, const void* src) {
    uint32_t d = (uint32_t)__cvta_generic_to_shared(dst);
    asm volatile("cp.async.cg.shared.global [%0], [%1], 16;\n" :: "r"(d), "l"(src));
}

// smem layout (dynamic): As[buf][hl][128][40], Bs[buf][hl][64][40]
#define AS(p, buf, hl, r, c) (p)[((((buf)*2 + (hl))*128 + (r))*40) + (c)]
#define BS(p, buf, hl, r, c) (p)[((((buf)*2 + (hl))*64  + (r))*40) + (c)]
#define GEMM_SMEM ((2*2*128*40 + 2*2*64*40) * 2)   // 61440 bytes

template<int MODE>
__global__ __launch_bounds__(256)
void gemm_bf16s(const float* __restrict__ bias,
                float* __restrict__ C, int M, int N, int K)
{
    extern __shared__ __nv_bfloat16 smem[];
    __nv_bfloat16* Asm = smem;
    __nv_bfloat16* Bsm = smem + 2*2*128*40;

    const __nv_bfloat16* AH = (MODE == 0) ? g_xH : g_outsH;
    const __nv_bfloat16* AL = (MODE == 0) ? g_xL : g_outsL;
    const __nv_bfloat16* WH = (MODE == 0) ? g_w1H : g_w2H;
    const __nv_bfloat16* WL = (MODE == 0) ? g_w1L : g_w2L;

    const int tid = threadIdx.x;
    const int wid = tid >> 5, lane = tid & 31;
    const int wm = wid >> 1, wn = wid & 1;
    const int groupID = lane >> 2, tig = lane & 3;
    const int bm0 = blockIdx.y * 128;
    const int bn0 = blockIdx.x * 64;
    const int KT = K / 32;

    // A chunk mapping: chunk c -> row c>>2, 16B-slot c&3; thread does c=tid, tid+256
    const int ar0 = tid >> 2,        aq0 = (tid & 3) * 8;
    const int ar1 = (tid + 256) >> 2, aq1 = aq0;
    const int br  = tid >> 2,        bq  = (tid & 3) * 8;

    float acc[2][4][4];
    #pragma unroll
    for (int mi = 0; mi < 2; mi++)
        #pragma unroll
        for (int ni = 0; ni < 4; ni++)
            #pragma unroll
            for (int j = 0; j < 4; j++) acc[mi][ni][j] = 0.f;

    auto load_tile = [&](int kt, int buf) {
        int k0 = kt * 32;
        cp16(&AS(Asm, buf, 0, ar0, aq0), AH + (size_t)(bm0 + ar0)*K + k0 + aq0);
        cp16(&AS(Asm, buf, 0, ar1, aq1), AH + (size_t)(bm0 + ar1)*K + k0 + aq1);
        cp16(&AS(Asm, buf, 1, ar0, aq0), AL + (size_t)(bm0 + ar0)*K + k0 + aq0);
        cp16(&AS(Asm, buf, 1, ar1, aq1), AL + (size_t)(bm0 + ar1)*K + k0 + aq1);
        cp16(&BS(Bsm, buf, 0, br, bq),   WH + (size_t)(bn0 + br)*K + k0 + bq);
        cp16(&BS(Bsm, buf, 1, br, bq),   WL + (size_t)(bn0 + br)*K + k0 + bq);
    };

    load_tile(0, 0);
    asm volatile("cp.async.commit_group;\n");

    for (int kt = 0; kt < KT; kt++) {
        const int buf = kt & 1;
        if (kt + 1 < KT) {
            load_tile(kt + 1, (kt + 1) & 1);
            asm volatile("cp.async.commit_group;\n");
            asm volatile("cp.async.wait_group 1;\n");
        } else {
            asm volatile("cp.async.wait_group 0;\n");
        }
        __syncthreads();

        #pragma unroll
        for (int kk = 0; kk < 2; kk++) {
            const int kb = kk * 16;
            uint32_t aH[2][4], aL[2][4], bH[4][2], bL[4][2];
            #pragma unroll
            for (int mi = 0; mi < 2; mi++) {
                int r0 = wm*32 + mi*16 + groupID;
                int r1 = r0 + 8;
                aH[mi][0] = *(const uint32_t*)&AS(Asm, buf, 0, r0, kb + 2*tig);
                aH[mi][1] = *(const uint32_t*)&AS(Asm, buf, 0, r1, kb + 2*tig);
                aH[mi][2] = *(const uint32_t*)&AS(Asm, buf, 0, r0, kb + 2*tig + 8);
                aH[mi][3] = *(const uint32_t*)&AS(Asm, buf, 0, r1, kb + 2*tig + 8);
                aL[mi][0] = *(const uint32_t*)&AS(Asm, buf, 1, r0, kb + 2*tig);
                aL[mi][1] = *(const uint32_t*)&AS(Asm, buf, 1, r1, kb + 2*tig);
                aL[mi][2] = *(const uint32_t*)&AS(Asm, buf, 1, r0, kb + 2*tig + 8);
                aL[mi][3] = *(const uint32_t*)&AS(Asm, buf, 1, r1, kb + 2*tig + 8);
            }
            #pragma unroll
            for (int ni = 0; ni < 4; ni++) {
                int cc = wn*32 + ni*8 + groupID;
                bH[ni][0] = *(const uint32_t*)&BS(Bsm, buf, 0, cc, kb + 2*tig);
                bH[ni][1] = *(const uint32_t*)&BS(Bsm, buf, 0, cc, kb + 2*tig + 8);
                bL[ni][0] = *(const uint32_t*)&BS(Bsm, buf, 1, cc, kb + 2*tig);
                bL[ni][1] = *(const uint32_t*)&BS(Bsm, buf, 1, cc, kb + 2*tig + 8);
            }
            #pragma unroll
            for (int mi = 0; mi < 2; mi++)
                #pragma unroll
                for (int ni = 0; ni < 4; ni++) {
                    MMA16816(acc[mi][ni], aH[mi], bH[ni]);
                    MMA16816(acc[mi][ni], aH[mi], bL[ni]);
                    MMA16816(acc[mi][ni], aL[mi], bH[ni]);
                }
        }
        __syncthreads();
    }

    // ---- epilogue ----
    #pragma unroll
    for (int mi = 0; mi < 2; mi++) {
        #pragma unroll
        for (int ni = 0; ni < 4; ni++) {
            int r0 = bm0 + wm*32 + mi*16 + groupID;
            int c0 = bn0 + wn*32 + ni*8 + 2*tig;
            float v00 = acc[mi][ni][0], v01 = acc[mi][ni][1];
            float v10 = acc[mi][ni][2], v11 = acc[mi][ni][3];
            if (MODE == 0) {
                #pragma unroll
                for (int q = 0; q < 4; q++) {
                    int rr = (q < 2) ? r0 : (r0 + 8);
                    int cc = (q & 1) ? (c0 + 1) : c0;
                    float vv = (q==0)?v00:(q==1)?v01:(q==2)?v10:v11;
                    if (cc < 512) g_u[(size_t)rr*512 + cc].x = vv;
                    else          g_u[(size_t)rr*512 + cc - 512].y = vv;
                }
            } else {
                float b0 = bias[c0], b1 = bias[c0 + 1];
                C[(size_t)r0*N + c0]         = v00 + b0;
                C[(size_t)r0*N + c0 + 1]     = v01 + b1;
                C[(size_t)(r0+8)*N + c0]     = v10 + b0;
                C[(size_t)(r0+8)*N + c0 + 1] = v11 + b1;
            }
        }
    }
}

// =========================================================================
extern "C" void kernel_launch(void* const* d_in, const int* in_sizes, int n_in,
                              void* d_out, int out_size)
{
    const float* x    = (const float*)d_in[0];
    const float* h0   = (const float*)d_in[1];
    const float* itoh = (const float*)d_in[2];
    const float* fcw  = (const float*)d_in[3];
    const float* fcb  = (const float*)d_in[4];
    const float* bh   = (const float*)d_in[5];
    const float* d1   = (const float*)d_in[6];
    const float* d2   = (const float*)d_in[7];
    const float* d3   = (const float*)d_in[8];
    const float* r1re = (const float*)d_in[9];
    const float* r1im = (const float*)d_in[10];
    const float* r2re = (const float*)d_in[11];
    const float* r2im = (const float*)d_in[12];
    const int*   perm = (const int*)d_in[13];
    float* out = (float*)d_out;

    cudaFuncSetAttribute(gemm_bf16s<0>, cudaFuncAttributeMaxDynamicSharedMemorySize, GEMM_SMEM);
    cudaFuncSetAttribute(gemm_bf16s<1>, cudaFuncAttributeMaxDynamicSharedMemorySize, GEMM_SMEM);

    // split conversions
    {
        int n4 = (MROWS*IN_) / 4;
        split_kernel<0><<<(n4 + 255)/256, 256>>>(x, n4);
        n4 = (2*H_*IN_) / 4;
        split_kernel<1><<<(n4 + 255)/256, 256>>>(itoh, n4);
        n4 = (OUT_*2*H_) / 4;
        split_kernel<2><<<(n4 + 255)/256, 256>>>(fcw, n4);
    }

    // GEMM1: u = x @ itoh^T  (M=32768, N=1024, K=256) -> g_u
    gemm_bf16s<0><<<dim3(1024/64, MROWS/128), 256, GEMM_SMEM>>>(nullptr, nullptr,
                                                                MROWS, 1024, 256);
    // scan
    scan_kernel<<<B_, 128>>>(h0, bh, d1, d2, d3, r1re, r1im, r2re, r2im, perm, out);
    // GEMM2: outputs = outs @ fc_w^T + fc_b  (M=32768, N=256, K=1024)
    gemm_bf16s<1><<<dim3(256/64, MROWS/128), 256, GEMM_SMEM>>>(fcb, out,
                                                               MROWS, 256, 1024);
}